// round 15
// baseline (speedup 1.0000x reference)
#include <cuda_runtime.h>
#include <cuda_bf16.h>
#include <math.h>

#define NMAX    50000
#define EMAX    800000
#define DMODEL  128
#define ALPHA   0.2f
#define LN_EPS  1e-5f

// K=128 bf16 => 64 u32 per row; stride 68 (4 pad) => ldmatrix rows CF.
#define TSTRIDE 68
#define SCAN_BLK 1024

// ---------------- scratch (device globals; no allocations allowed) ----------
__device__ __align__(16) __nv_bfloat16 g_Qh[NMAX * DMODEL];
__device__ __align__(16) __nv_bfloat16 g_Kh[NMAX * DMODEL];
__device__ __align__(16) __nv_bfloat16 g_Vh[NMAX * DMODEL];
__device__ __align__(16) unsigned g_Wb32[3 * DMODEL * 64];   // Wq,Wk,Wv bf16x2
__device__ __align__(16) unsigned g_Wob32[DMODEL * 64];      // Wo bf16x2
__device__ __align__(16) int   g_cnt[NMAX];
__device__ __align__(16) int   g_off[NMAX + 1];
__device__ __align__(16) int   g_cur[NMAX];
__device__ __align__(16) int   g_bsum[(NMAX + SCAN_BLK - 1) / SCAN_BLK + 1];
__device__ __align__(16) int2  g_se[EMAX + 64];   // {row, ew bits} per CSR slot
__device__ int g_is64;

// ---------------- bf16 mma / ldmatrix helpers --------------------------------
__device__ __forceinline__ void mma_bf16(float c[4],
                                         unsigned a0, unsigned a1,
                                         unsigned a2, unsigned a3,
                                         unsigned b0, unsigned b1)
{
    asm("mma.sync.aligned.m16n8k16.row.col.f32.bf16.bf16.f32 "
        "{%0,%1,%2,%3}, {%4,%5,%6,%7}, {%8,%9}, {%0,%1,%2,%3};"
        : "+f"(c[0]), "+f"(c[1]), "+f"(c[2]), "+f"(c[3])
        : "r"(a0), "r"(a1), "r"(a2), "r"(a3), "r"(b0), "r"(b1));
}

__device__ __forceinline__ void ldmx4(unsigned& r0, unsigned& r1,
                                      unsigned& r2, unsigned& r3,
                                      unsigned addr)
{
    asm volatile("ldmatrix.sync.aligned.m8n8.x4.shared.b16 {%0,%1,%2,%3}, [%4];"
                 : "=r"(r0), "=r"(r1), "=r"(r2), "=r"(r3) : "r"(addr));
}

__device__ __forceinline__ unsigned pack_bf16x2(float lo, float hi)
{
    __nv_bfloat162 h = __floats2bfloat162_rn(lo, hi);
    return *reinterpret_cast<unsigned*>(&h);
}

__device__ __forceinline__ void cp_async16(unsigned smem_dst, const void* gsrc)
{
    asm volatile("cp.async.cg.shared.global [%0], [%1], 16;"
                 :: "r"(smem_dst), "l"(gsrc));
}
__device__ __forceinline__ void cp_async_wait_all()
{
    asm volatile("cp.async.commit_group;");
    asm volatile("cp.async.wait_group 0;");
}

__device__ __forceinline__ int edge_col(const void* eiv, int E, int e)
{
    return g_is64 ? (int)reinterpret_cast<const long long*>(eiv)[(long long)E + e]
                  : reinterpret_cast<const int*>(eiv)[E + e];
}
__device__ __forceinline__ int edge_row(const void* eiv, int E, int e)
{
    return g_is64 ? (int)reinterpret_cast<const long long*>(eiv)[e]
                  : reinterpret_cast<const int*>(eiv)[e];
}

// ---------------- wprep: dtype detect + bf16 weights + zero histogram -------
__global__ void wprep_kernel(const unsigned* __restrict__ ei,
                             const float* __restrict__ Wq,
                             const float* __restrict__ Wk,
                             const float* __restrict__ Wv,
                             const float* __restrict__ Wo,
                             int n, int E)
{
    int i = blockIdx.x * blockDim.x + threadIdx.x;
    if (i == 0) {
        int is64 = 1;
        int m = (E >= 64) ? 64 : E;
        for (int j = 0; j < m; j++) {
            if (ei[2 * j + 1] != 0u) { is64 = 0; break; }
        }
        g_is64 = is64;
    }
    if (i < DMODEL * 64) {
        const float2* q2 = reinterpret_cast<const float2*>(Wq);
        const float2* k2 = reinterpret_cast<const float2*>(Wk);
        const float2* v2 = reinterpret_cast<const float2*>(Wv);
        const float2* o2 = reinterpret_cast<const float2*>(Wo);
        float2 a;
        a = q2[i]; g_Wb32[i]                   = pack_bf16x2(a.x, a.y);
        a = k2[i]; g_Wb32[DMODEL * 64 + i]     = pack_bf16x2(a.x, a.y);
        a = v2[i]; g_Wb32[2 * DMODEL * 64 + i] = pack_bf16x2(a.x, a.y);
        a = o2[i]; g_Wob32[i]                  = pack_bf16x2(a.x, a.y);
    }
    const int total = gridDim.x * blockDim.x;
    for (int j = i; j < n; j += total) g_cnt[j] = 0;
}

// ---------------- histogram of destination degrees ---------------------------
__global__ void hist_kernel(const void* __restrict__ eiv, int E)
{
    int e = blockIdx.x * blockDim.x + threadIdx.x;
    if (e >= E) return;
    atomicAdd(&g_cnt[edge_col(eiv, E, e)], 1);
}

// ---------------- two-level scan ---------------------------------------------
__global__ void scanA_kernel(int n)
{
    __shared__ int ts[256];
    const int t    = threadIdx.x;
    const int base = blockIdx.x * SCAN_BLK;
    const int idx  = base + t * 4;

    int c0 = 0, c1 = 0, c2 = 0, c3 = 0;
    if (idx + 3 < n) {
        int4 v = *reinterpret_cast<const int4*>(&g_cnt[idx]);
        c0 = v.x; c1 = v.y; c2 = v.z; c3 = v.w;
    } else {
        if (idx + 0 < n) c0 = g_cnt[idx + 0];
        if (idx + 1 < n) c1 = g_cnt[idx + 1];
        if (idx + 2 < n) c2 = g_cnt[idx + 2];
        if (idx + 3 < n) c3 = g_cnt[idx + 3];
    }
    int s = c0 + c1 + c2 + c3;
    ts[t] = s;
    __syncthreads();
#pragma unroll
    for (int off = 1; off < 256; off <<= 1) {
        int v = (t >= off) ? ts[t - off] : 0;
        __syncthreads();
        ts[t] += v;
        __syncthreads();
    }
    int run = (t == 0) ? 0 : ts[t - 1];
    if (idx + 0 < n) { g_off[idx + 0] = run; run += c0; }
    if (idx + 1 < n) { g_off[idx + 1] = run; run += c1; }
    if (idx + 2 < n) { g_off[idx + 2] = run; run += c2; }
    if (idx + 3 < n) { g_off[idx + 3] = run; run += c3; }
    if (t == 255) g_bsum[blockIdx.x] = ts[255];
}

__global__ void scanC_kernel(int n)
{
    __shared__ int boff_s;
    const int chunk = blockIdx.x >> 2;
    if (threadIdx.x < 32) {
        int v = 0;
        for (int j = threadIdx.x; j < chunk; j += 32) v += g_bsum[j];
#pragma unroll
        for (int off = 16; off >= 1; off >>= 1)
            v += __shfl_xor_sync(0xffffffffu, v, off);
        if (threadIdx.x == 0) boff_s = v;
    }
    __syncthreads();
    int i = blockIdx.x * 256 + threadIdx.x;
    if (i >= n) return;
    int o = g_off[i] + boff_s;
    g_off[i] = o;
    g_cur[i] = o;
    if (i == n - 1) g_off[n] = o + g_cnt[i];
}

// ---------------- scatter: permute (row, gate) into CSR order ----------------
__global__ void scatter_kernel(const void* __restrict__ eiv,
                               const float* __restrict__ eattr,
                               int E)
{
    int e = blockIdx.x * blockDim.x + threadIdx.x;
    if (e >= E) return;
    int row = edge_row(eiv, E, e);
    int col = edge_col(eiv, E, e);

    const float4* a4 = reinterpret_cast<const float4*>(eattr) + (size_t)e * 4;
    float s = 0.f;
#pragma unroll
    for (int i = 0; i < 4; i++) {
        float4 a = a4[i];
        s += a.x + a.y + a.z + a.w;
    }
    float ew = 1.f / (1.f + __expf(-s));

    int pos = atomicAdd(&g_cur[col], 1);
    g_se[pos] = make_int2(row, __float_as_int(ew));
}

// ---------------- fused QKV projection GEMM (bf16 MMA + ldmatrix) -----------
#define QKV_SMEM ((128 * TSTRIDE + 64 * TSTRIDE) * 4)

__global__ void __launch_bounds__(256, 3)
qkv_kernel(const float* __restrict__ x, int n)
{
    extern __shared__ unsigned smu[];
    unsigned* xs = smu;                   // [128][68] bf16x2 (64 used)
    unsigned* ws = smu + 128 * TSTRIDE;   // [64][68]  bf16x2

    const int row0 = blockIdx.x * 128;
    const int h    = blockIdx.y;
    const int tid  = threadIdx.x;
    const int warp = tid >> 5;
    const int lane = tid & 31;
    const int g    = lane >> 2;
    const int tg   = lane & 3;
    const int rb   = (warp & 3) * 32;
    const int cb   = (warp >> 2) * 32;

    const unsigned ws_base = (unsigned)__cvta_generic_to_shared(ws);
    const unsigned xs_base = (unsigned)__cvta_generic_to_shared(xs);

    const int quad = lane >> 3;
    const int r8   = lane & 7;
    unsigned aaddr[2], baddr[2];
#pragma unroll
    for (int mt = 0; mt < 2; mt++)
        aaddr[mt] = xs_base +
            ((rb + mt * 16 + (quad & 1) * 8 + r8) * TSTRIDE) * 4 +
            (quad >> 1) * 16;
#pragma unroll
    for (int p = 0; p < 2; p++)
        baddr[p] = ws_base +
            ((cb + (p * 2 + (quad >> 1)) * 8 + r8) * TSTRIDE) * 4 +
            (quad & 1) * 16;

    for (int t = tid; t < 128 * 32; t += 256) {
        int r  = t >> 5;
        int c4 = t & 31;
        float4 v = make_float4(0.f, 0.f, 0.f, 0.f);
        int gr = row0 + r;
        if (gr < n) v = reinterpret_cast<const float4*>(x)[gr * 32 + c4];
        unsigned u0 = pack_bf16x2(v.x, v.y);
        unsigned u1 = pack_bf16x2(v.z, v.w);
        unsigned long long u64v =
            (unsigned long long)u0 | ((unsigned long long)u1 << 32);
        *reinterpret_cast<unsigned long long*>(xs + r * TSTRIDE + c4 * 2) = u64v;
    }

    __nv_bfloat16* Os[3] = {g_Qh, g_Kh, g_Vh};

    for (int w = 0; w < 3; w++) {
        __syncthreads();
        const unsigned* Wsrc = g_Wb32 + (w * DMODEL + h * 64) * 64;
        for (int t = tid; t < 64 * 16; t += 256) {
            int r   = t >> 4;
            int c16 = t & 15;
            cp_async16(ws_base + (r * TSTRIDE + c16 * 4) * 4,
                       Wsrc + r * 64 + c16 * 4);
        }
        cp_async_wait_all();
        __syncthreads();

        float c[2][4][4];
#pragma unroll
        for (int mt = 0; mt < 2; mt++)
#pragma unroll
            for (int nt = 0; nt < 4; nt++)
#pragma unroll
                for (int i = 0; i < 4; i++) c[mt][nt][i] = 0.f;

#pragma unroll
        for (int kt = 0; kt < 8; kt++) {
            const unsigned off = kt * 32;
            unsigned a[2][4], b[2][4];
            ldmx4(a[0][0], a[0][1], a[0][2], a[0][3], aaddr[0] + off);
            ldmx4(a[1][0], a[1][1], a[1][2], a[1][3], aaddr[1] + off);
            ldmx4(b[0][0], b[0][1], b[0][2], b[0][3], baddr[0] + off);
            ldmx4(b[1][0], b[1][1], b[1][2], b[1][3], baddr[1] + off);
#pragma unroll
            for (int p = 0; p < 2; p++)
#pragma unroll
                for (int q = 0; q < 2; q++) {
                    const int nt = p * 2 + q;
                    mma_bf16(c[0][nt], a[0][0], a[0][1], a[0][2], a[0][3],
                             b[p][2 * q], b[p][2 * q + 1]);
                    mma_bf16(c[1][nt], a[1][0], a[1][1], a[1][2], a[1][3],
                             b[p][2 * q], b[p][2 * q + 1]);
                }
        }

        const float scale = (w == 0) ? 0.25f : 1.0f;
        __nv_bfloat162* OUT = reinterpret_cast<__nv_bfloat162*>(Os[w]);
#pragma unroll
        for (int mt = 0; mt < 2; mt++) {
#pragma unroll
            for (int nt = 0; nt < 4; nt++) {
                int cp = (h * 64 + cb + nt * 8 + 2 * tg) >> 1;
                int r1 = row0 + rb + mt * 16 + g;
                int r2 = r1 + 8;
                if (r1 < n)
                    OUT[r1 * 64 + cp] = __floats2bfloat162_rn(
                        c[mt][nt][0] * scale, c[mt][nt][1] * scale);
                if (r2 < n)
                    OUT[r2 * 64 + cp] = __floats2bfloat162_rn(
                        c[mt][nt][2] * scale, c[mt][nt][3] * scale);
            }
        }
    }
}

// ---------------- FUSED: edge aggregation + Wo GEMM + residual + LN ----------
// Phase 1: 8 warps aggregate 128 destination nodes (warp w -> rows w+8j),
//          writing bf16x2 results straight into the smem A-tile.
// Phase 2: Wo MMA (ldmatrix), res staging, residual + LayerNorm.
#define OUT_SMEM (128 * 132 * 4)

__global__ void __launch_bounds__(256, 2)
out_ln_kernel(const float* __restrict__ x,
              const float* __restrict__ bo,
              const float* __restrict__ gamma,
              const float* __restrict__ beta,
              float* __restrict__ out,
              int n)
{
    extern __shared__ unsigned smu[];
    unsigned* as = smu;                   // [128][68] bf16x2 AGG tile
    unsigned* ws = smu + 128 * TSTRIDE;   // [64][68]  bf16x2 Wo half
    float* res = reinterpret_cast<float*>(smu);  // [128][132] fp32 (aliases)

    const int row0 = blockIdx.x * 128;
    const int tid  = threadIdx.x;
    const int warp = tid >> 5;
    const int lane = tid & 31;
    const int g    = lane >> 2;
    const int tg   = lane & 3;
    const int rb   = (warp & 3) * 32;
    const int cb   = (warp >> 2) * 32;

    const unsigned ws_base = (unsigned)__cvta_generic_to_shared(ws);
    const unsigned as_base = (unsigned)__cvta_generic_to_shared(as);

    const int quad = lane >> 3;
    const int r8   = lane & 7;
    unsigned aaddr[2], baddr[2];
#pragma unroll
    for (int mt = 0; mt < 2; mt++)
        aaddr[mt] = as_base +
            ((rb + mt * 16 + (quad & 1) * 8 + r8) * TSTRIDE) * 4 +
            (quad >> 1) * 16;
#pragma unroll
    for (int p = 0; p < 2; p++)
        baddr[p] = ws_base +
            ((cb + (p * 2 + (quad >> 1)) * 8 + r8) * TSTRIDE) * 4 +
            (quad & 1) * 16;

    // ---- Phase 1: per-node edge aggregation into the A-tile -------------
    const int hw = lane >> 4;
    const int hl = lane & 15;
    const unsigned hmask = 0xFFFFu << (hw * 16);

    const uint4* Q4 = reinterpret_cast<const uint4*>(g_Qh);
    const uint4* K4 = reinterpret_cast<const uint4*>(g_Kh);
    const uint4* V4 = reinterpret_cast<const uint4*>(g_Vh);

    for (int j = 0; j < 16; j++) {
        const int r  = warp + 8 * j;     // local row 0..127
        const int gr = row0 + r;

        float2 a0 = {0.f, 0.f}, a1 = {0.f, 0.f},
               a2 = {0.f, 0.f}, a3 = {0.f, 0.f};

        if (gr < n) {
            const int start = __ldg(&g_off[gr]);
            const int end   = __ldg(&g_off[gr + 1]);

            uint4 ku = K4[gr * 16 + hl];
            float2 k0 = __bfloat1622float2(*reinterpret_cast<__nv_bfloat162*>(&ku.x));
            float2 k1 = __bfloat1622float2(*reinterpret_cast<__nv_bfloat162*>(&ku.y));
            float2 k2 = __bfloat1622float2(*reinterpret_cast<__nv_bfloat162*>(&ku.z));
            float2 k3 = __bfloat1622float2(*reinterpret_cast<__nv_bfloat162*>(&ku.w));

            for (int e = start + hw; e < end; e += 4) {
                const int has2 = (e + 2 < end);
                int2 se0 = __ldg(&g_se[e]);
                int2 se1 = has2 ? __ldg(&g_se[e + 2]) : se0;

                uint4 qu0 = Q4[se0.x * 16 + hl];
                uint4 vu0 = V4[se0.x * 16 + hl];
                uint4 qu1 = Q4[se1.x * 16 + hl];
                uint4 vu1 = V4[se1.x * 16 + hl];

                {
                    float ew = __int_as_float(se0.y);
                    float2 q0 = __bfloat1622float2(*reinterpret_cast<__nv_bfloat162*>(&qu0.x));
                    float2 q1 = __bfloat1622float2(*reinterpret_cast<__nv_bfloat162*>(&qu0.y));
                    float2 q2 = __bfloat1622float2(*reinterpret_cast<__nv_bfloat162*>(&qu0.z));
                    float2 q3 = __bfloat1622float2(*reinterpret_cast<__nv_bfloat162*>(&qu0.w));
                    float s = q0.x * k0.x + q0.y * k0.y + q1.x * k1.x + q1.y * k1.y +
                              q2.x * k2.x + q2.y * k2.y + q3.x * k3.x + q3.y * k3.y;
                    s += __shfl_xor_sync(hmask, s, 1);
                    s = (s > 0.f) ? s : ALPHA * s;
                    s *= ew;
                    float m = s;
                    m = fmaxf(m, __shfl_xor_sync(hmask, m, 2));
                    m = fmaxf(m, __shfl_xor_sync(hmask, m, 4));
                    m = fmaxf(m, __shfl_xor_sync(hmask, m, 8));
                    float p = __expf(s - m);
                    float den = p;
                    den += __shfl_xor_sync(hmask, den, 2);
                    den += __shfl_xor_sync(hmask, den, 4);
                    den += __shfl_xor_sync(hmask, den, 8);
                    p /= den;
                    float2 v0 = __bfloat1622float2(*reinterpret_cast<__nv_bfloat162*>(&vu0.x));
                    float2 v1 = __bfloat1622float2(*reinterpret_cast<__nv_bfloat162*>(&vu0.y));
                    float2 v2 = __bfloat1622float2(*reinterpret_cast<__nv_bfloat162*>(&vu0.z));
                    float2 v3 = __bfloat1622float2(*reinterpret_cast<__nv_bfloat162*>(&vu0.w));
                    a0.x += p * v0.x; a0.y += p * v0.y;
                    a1.x += p * v1.x; a1.y += p * v1.y;
                    a2.x += p * v2.x; a2.y += p * v2.y;
                    a3.x += p * v3.x; a3.y += p * v3.y;
                }
                if (has2) {
                    float ew = __int_as_float(se1.y);
                    float2 q0 = __bfloat1622float2(*reinterpret_cast<__nv_bfloat162*>(&qu1.x));
                    float2 q1 = __bfloat1622float2(*reinterpret_cast<__nv_bfloat162*>(&qu1.y));
                    float2 q2 = __bfloat1622float2(*reinterpret_cast<__nv_bfloat162*>(&qu1.z));
                    float2 q3 = __bfloat1622float2(*reinterpret_cast<__nv_bfloat162*>(&qu1.w));
                    float s = q0.x * k0.x + q0.y * k0.y + q1.x * k1.x + q1.y * k1.y +
                              q2.x * k2.x + q2.y * k2.y + q3.x * k3.x + q3.y * k3.y;
                    s += __shfl_xor_sync(hmask, s, 1);
                    s = (s > 0.f) ? s : ALPHA * s;
                    s *= ew;
                    float m = s;
                    m = fmaxf(m, __shfl_xor_sync(hmask, m, 2));
                    m = fmaxf(m, __shfl_xor_sync(hmask, m, 4));
                    m = fmaxf(m, __shfl_xor_sync(hmask, m, 8));
                    float p = __expf(s - m);
                    float den = p;
                    den += __shfl_xor_sync(hmask, den, 2);
                    den += __shfl_xor_sync(hmask, den, 4);
                    den += __shfl_xor_sync(hmask, den, 8);
                    p /= den;
                    float2 v0 = __bfloat1622float2(*reinterpret_cast<__nv_bfloat162*>(&vu1.x));
                    float2 v1 = __bfloat1622float2(*reinterpret_cast<__nv_bfloat162*>(&vu1.y));
                    float2 v2 = __bfloat1622float2(*reinterpret_cast<__nv_bfloat162*>(&vu1.z));
                    float2 v3 = __bfloat1622float2(*reinterpret_cast<__nv_bfloat162*>(&vu1.w));
                    a0.x += p * v0.x; a0.y += p * v0.y;
                    a1.x += p * v1.x; a1.y += p * v1.y;
                    a2.x += p * v2.x; a2.y += p * v2.y;
                    a3.x += p * v3.x; a3.y += p * v3.y;
                }
            }
        }

        // combine halves (full warp convergent)
        a0.x += __shfl_xor_sync(0xffffffffu, a0.x, 16);
        a0.y += __shfl_xor_sync(0xffffffffu, a0.y, 16);
        a1.x += __shfl_xor_sync(0xffffffffu, a1.x, 16);
        a1.y += __shfl_xor_sync(0xffffffffu, a1.y, 16);
        a2.x += __shfl_xor_sync(0xffffffffu, a2.x, 16);
        a2.y += __shfl_xor_sync(0xffffffffu, a2.y, 16);
        a3.x += __shfl_xor_sync(0xffffffffu, a3.x, 16);
        a3.y += __shfl_xor_sync(0xffffffffu, a3.y, 16);

        if (hw == 0) {
            uint4 u;
            u.x = pack_bf16x2(a0.x, a0.y);
            u.y = pack_bf16x2(a1.x, a1.y);
            u.z = pack_bf16x2(a2.x, a2.y);
            u.w = pack_bf16x2(a3.x, a3.y);
            *reinterpret_cast<uint4*>(as + r * TSTRIDE + hl * 4) = u;
        }
    }

    // ---- Phase 2: Wo GEMM + residual + LayerNorm ------------------------
    float c[2][2][4][4];
#pragma unroll
    for (int h = 0; h < 2; h++)
#pragma unroll
        for (int mt = 0; mt < 2; mt++)
#pragma unroll
            for (int nt = 0; nt < 4; nt++)
#pragma unroll
                for (int i = 0; i < 4; i++) c[h][mt][nt][i] = 0.f;

    for (int h = 0; h < 2; h++) {
        __syncthreads();
        const unsigned* Wsrc = g_Wob32 + (h * 64) * 64;
        for (int t = tid; t < 64 * 16; t += 256) {
            int r   = t >> 4;
            int c16 = t & 15;
            cp_async16(ws_base + (r * TSTRIDE + c16 * 4) * 4,
                       Wsrc + r * 64 + c16 * 4);
        }
        cp_async_wait_all();
        __syncthreads();

#pragma unroll
        for (int kt = 0; kt < 8; kt++) {
            const unsigned off = kt * 32;
            unsigned a[2][4], b[2][4];
            ldmx4(a[0][0], a[0][1], a[0][2], a[0][3], aaddr[0] + off);
            ldmx4(a[1][0], a[1][1], a[1][2], a[1][3], aaddr[1] + off);
            ldmx4(b[0][0], b[0][1], b[0][2], b[0][3], baddr[0] + off);
            ldmx4(b[1][0], b[1][1], b[1][2], b[1][3], baddr[1] + off);
#pragma unroll
            for (int p = 0; p < 2; p++)
#pragma unroll
                for (int q = 0; q < 2; q++) {
                    const int nt = p * 2 + q;
                    mma_bf16(c[h][0][nt], a[0][0], a[0][1], a[0][2], a[0][3],
                             b[p][2 * q], b[p][2 * q + 1]);
                    mma_bf16(c[h][1][nt], a[1][0], a[1][1], a[1][2], a[1][3],
                             b[p][2 * q], b[p][2 * q + 1]);
                }
        }
    }

    __syncthreads();
#pragma unroll
    for (int h = 0; h < 2; h++)
#pragma unroll
        for (int mt = 0; mt < 2; mt++)
#pragma unroll
            for (int nt = 0; nt < 4; nt++) {
                int r1 = rb + mt * 16 + g;
                int cc = h * 64 + cb + nt * 8 + 2 * tg;
                res[r1 * 132 + cc]           = c[h][mt][nt][0];
                res[r1 * 132 + cc + 1]       = c[h][mt][nt][1];
                res[(r1 + 8) * 132 + cc]     = c[h][mt][nt][2];
                res[(r1 + 8) * 132 + cc + 1] = c[h][mt][nt][3];
            }
    __syncthreads();

    float4 bo4 = reinterpret_cast<const float4*>(bo)[lane];
    float4 g4  = reinterpret_cast<const float4*>(gamma)[lane];
    float4 b4  = reinterpret_cast<const float4*>(beta)[lane];

    for (int r = warp; r < 128; r += 8) {
        int gr = row0 + r;
        if (gr >= n) continue;
        float4 a  = *reinterpret_cast<float4*>(res + r * 132 + lane * 4);
        float4 xv = reinterpret_cast<const float4*>(x)[gr * 32 + lane];
        float o0 = a.x + bo4.x + xv.x;
        float o1 = a.y + bo4.y + xv.y;
        float o2 = a.z + bo4.z + xv.z;
        float o3 = a.w + bo4.w + xv.w;

        float s  = o0 + o1 + o2 + o3;
        float ss = o0 * o0 + o1 * o1 + o2 * o2 + o3 * o3;
#pragma unroll
        for (int off = 16; off >= 1; off >>= 1) {
            s  += __shfl_xor_sync(0xffffffffu, s,  off);
            ss += __shfl_xor_sync(0xffffffffu, ss, off);
        }
        float mu  = s * (1.f / 128.f);
        float var = ss * (1.f / 128.f) - mu * mu;
        float inv = rsqrtf(var + LN_EPS);

        float4 o;
        o.x = (o0 - mu) * inv * g4.x + b4.x;
        o.y = (o1 - mu) * inv * g4.y + b4.y;
        o.z = (o2 - mu) * inv * g4.z + b4.z;
        o.w = (o3 - mu) * inv * g4.w + b4.w;
        reinterpret_cast<float4*>(out)[gr * 32 + lane] = o;
    }
}

// ---------------- launcher ---------------------------------------------------
extern "C" void kernel_launch(void* const* d_in, const int* in_sizes, int n_in,
                              void* d_out, int out_size)
{
    const float* x     = (const float*)d_in[0];
    const void*  ei    = d_in[1];
    const float* eattr = (const float*)d_in[2];
    const float* Wq    = (const float*)d_in[3];
    const float* Wk    = (const float*)d_in[4];
    const float* Wv    = (const float*)d_in[5];
    const float* Wo    = (const float*)d_in[6];
    const float* bo    = (const float*)d_in[7];
    const float* gamma = (const float*)d_in[8];
    const float* beta  = (const float*)d_in[9];
    float* out = (float*)d_out;

    int n = in_sizes[0] / DMODEL;
    int E = in_sizes[1] / 2;
    if (n > NMAX) n = NMAX;
    if (E > EMAX) E = EMAX;

    cudaFuncSetAttribute(qkv_kernel,
                         cudaFuncAttributeMaxDynamicSharedMemorySize, QKV_SMEM);
    cudaFuncSetAttribute(out_ln_kernel,
                         cudaFuncAttributeMaxDynamicSharedMemorySize, OUT_SMEM);

    int nsb = (n + SCAN_BLK - 1) / SCAN_BLK;

    wprep_kernel<<<32, 256>>>((const unsigned*)ei, Wq, Wk, Wv, Wo, n, E);
    hist_kernel<<<(E + 255) / 256, 256>>>(ei, E);
    scanA_kernel<<<nsb, 256>>>(n);
    scanC_kernel<<<(n + 255) / 256, 256>>>(n);
    scatter_kernel<<<(E + 255) / 256, 256>>>(ei, eattr, E);

    int nrb = (n + 127) / 128;
    qkv_kernel<<<dim3(nrb, 2), 256, QKV_SMEM>>>(x, n);

    out_ln_kernel<<<nrb, 256, OUT_SMEM>>>(x, bo, gamma, beta, out, n);
}

// round 16
// speedup vs baseline: 1.4146x; 1.4146x over previous
#include <cuda_runtime.h>
#include <cuda_bf16.h>
#include <math.h>

#define NMAX    50000
#define EMAX    800000
#define DMODEL  128
#define ALPHA   0.2f
#define LN_EPS  1e-5f

// K=128 bf16 => 64 u32 per row; stride 68 (4 pad) => ldmatrix rows CF.
#define TSTRIDE 68
#define SCAN_BLK 1024

// ---------------- scratch (device globals; no allocations allowed) ----------
__device__ __align__(16) __nv_bfloat16 g_Qh[NMAX * DMODEL];
__device__ __align__(16) __nv_bfloat16 g_Kh[NMAX * DMODEL];
__device__ __align__(16) __nv_bfloat16 g_Vh[NMAX * DMODEL];
__device__ __align__(16) __nv_bfloat16 g_AGGh[NMAX * DMODEL];   // bf16 AGG
__device__ __align__(16) unsigned g_Wb32[3 * DMODEL * 64];   // Wq,Wk,Wv bf16x2
__device__ __align__(16) unsigned g_Wob32[DMODEL * 64];      // Wo bf16x2
__device__ __align__(16) int   g_cnt[NMAX];
__device__ __align__(16) int   g_off[NMAX + 1];
__device__ __align__(16) int   g_cur[NMAX];
__device__ __align__(16) int   g_bsum[(NMAX + SCAN_BLK - 1) / SCAN_BLK + 1];
__device__ __align__(16) int2  g_se[EMAX + 64];   // {row, ew bits} per CSR slot
__device__ int g_is64;

// ---------------- bf16 mma / ldmatrix helpers --------------------------------
__device__ __forceinline__ void mma_bf16(float c[4],
                                         unsigned a0, unsigned a1,
                                         unsigned a2, unsigned a3,
                                         unsigned b0, unsigned b1)
{
    asm("mma.sync.aligned.m16n8k16.row.col.f32.bf16.bf16.f32 "
        "{%0,%1,%2,%3}, {%4,%5,%6,%7}, {%8,%9}, {%0,%1,%2,%3};"
        : "+f"(c[0]), "+f"(c[1]), "+f"(c[2]), "+f"(c[3])
        : "r"(a0), "r"(a1), "r"(a2), "r"(a3), "r"(b0), "r"(b1));
}

__device__ __forceinline__ void ldmx4(unsigned& r0, unsigned& r1,
                                      unsigned& r2, unsigned& r3,
                                      unsigned addr)
{
    asm volatile("ldmatrix.sync.aligned.m8n8.x4.shared.b16 {%0,%1,%2,%3}, [%4];"
                 : "=r"(r0), "=r"(r1), "=r"(r2), "=r"(r3) : "r"(addr));
}

__device__ __forceinline__ unsigned pack_bf16x2(float lo, float hi)
{
    __nv_bfloat162 h = __floats2bfloat162_rn(lo, hi);
    return *reinterpret_cast<unsigned*>(&h);
}

__device__ __forceinline__ void cp_async16(unsigned smem_dst, const void* gsrc)
{
    asm volatile("cp.async.cg.shared.global [%0], [%1], 16;"
                 :: "r"(smem_dst), "l"(gsrc));
}
__device__ __forceinline__ void cp_async_wait_all()
{
    asm volatile("cp.async.commit_group;");
    asm volatile("cp.async.wait_group 0;");
}

__device__ __forceinline__ int edge_col(const void* eiv, int E, int e)
{
    return g_is64 ? (int)reinterpret_cast<const long long*>(eiv)[(long long)E + e]
                  : reinterpret_cast<const int*>(eiv)[E + e];
}
__device__ __forceinline__ int edge_row(const void* eiv, int E, int e)
{
    return g_is64 ? (int)reinterpret_cast<const long long*>(eiv)[e]
                  : reinterpret_cast<const int*>(eiv)[e];
}

// ---------------- wprep: dtype detect + bf16 weights + zero histogram -------
__global__ void wprep_kernel(const unsigned* __restrict__ ei,
                             const float* __restrict__ Wq,
                             const float* __restrict__ Wk,
                             const float* __restrict__ Wv,
                             const float* __restrict__ Wo,
                             int n, int E)
{
    int i = blockIdx.x * blockDim.x + threadIdx.x;
    if (i == 0) {
        int is64 = 1;
        int m = (E >= 64) ? 64 : E;
        for (int j = 0; j < m; j++) {
            if (ei[2 * j + 1] != 0u) { is64 = 0; break; }
        }
        g_is64 = is64;
    }
    if (i < DMODEL * 64) {
        const float2* q2 = reinterpret_cast<const float2*>(Wq);
        const float2* k2 = reinterpret_cast<const float2*>(Wk);
        const float2* v2 = reinterpret_cast<const float2*>(Wv);
        const float2* o2 = reinterpret_cast<const float2*>(Wo);
        float2 a;
        a = q2[i]; g_Wb32[i]                   = pack_bf16x2(a.x, a.y);
        a = k2[i]; g_Wb32[DMODEL * 64 + i]     = pack_bf16x2(a.x, a.y);
        a = v2[i]; g_Wb32[2 * DMODEL * 64 + i] = pack_bf16x2(a.x, a.y);
        a = o2[i]; g_Wob32[i]                  = pack_bf16x2(a.x, a.y);
    }
    const int total = gridDim.x * blockDim.x;
    for (int j = i; j < n; j += total) g_cnt[j] = 0;
}

// ---------------- histogram of destination degrees ---------------------------
__global__ void hist_kernel(const void* __restrict__ eiv, int E)
{
    int e = blockIdx.x * blockDim.x + threadIdx.x;
    if (e >= E) return;
    atomicAdd(&g_cnt[edge_col(eiv, E, e)], 1);
}

// ---------------- two-level scan ---------------------------------------------
__global__ void scanA_kernel(int n)
{
    __shared__ int ts[256];
    const int t    = threadIdx.x;
    const int base = blockIdx.x * SCAN_BLK;
    const int idx  = base + t * 4;

    int c0 = 0, c1 = 0, c2 = 0, c3 = 0;
    if (idx + 3 < n) {
        int4 v = *reinterpret_cast<const int4*>(&g_cnt[idx]);
        c0 = v.x; c1 = v.y; c2 = v.z; c3 = v.w;
    } else {
        if (idx + 0 < n) c0 = g_cnt[idx + 0];
        if (idx + 1 < n) c1 = g_cnt[idx + 1];
        if (idx + 2 < n) c2 = g_cnt[idx + 2];
        if (idx + 3 < n) c3 = g_cnt[idx + 3];
    }
    int s = c0 + c1 + c2 + c3;
    ts[t] = s;
    __syncthreads();
#pragma unroll
    for (int off = 1; off < 256; off <<= 1) {
        int v = (t >= off) ? ts[t - off] : 0;
        __syncthreads();
        ts[t] += v;
        __syncthreads();
    }
    int run = (t == 0) ? 0 : ts[t - 1];
    if (idx + 0 < n) { g_off[idx + 0] = run; run += c0; }
    if (idx + 1 < n) { g_off[idx + 1] = run; run += c1; }
    if (idx + 2 < n) { g_off[idx + 2] = run; run += c2; }
    if (idx + 3 < n) { g_off[idx + 3] = run; run += c3; }
    if (t == 255) g_bsum[blockIdx.x] = ts[255];
}

__global__ void scanC_kernel(int n)
{
    __shared__ int boff_s;
    const int chunk = blockIdx.x >> 2;
    if (threadIdx.x < 32) {
        int v = 0;
        for (int j = threadIdx.x; j < chunk; j += 32) v += g_bsum[j];
#pragma unroll
        for (int off = 16; off >= 1; off >>= 1)
            v += __shfl_xor_sync(0xffffffffu, v, off);
        if (threadIdx.x == 0) boff_s = v;
    }
    __syncthreads();
    int i = blockIdx.x * 256 + threadIdx.x;
    if (i >= n) return;
    int o = g_off[i] + boff_s;
    g_off[i] = o;
    g_cur[i] = o;
    if (i == n - 1) g_off[n] = o + g_cnt[i];
}

// ---------------- scatter: permute (row, gate) into CSR order ----------------
__global__ void scatter_kernel(const void* __restrict__ eiv,
                               const float* __restrict__ eattr,
                               int E)
{
    int e = blockIdx.x * blockDim.x + threadIdx.x;
    if (e >= E) return;
    int row = edge_row(eiv, E, e);
    int col = edge_col(eiv, E, e);

    const float4* a4 = reinterpret_cast<const float4*>(eattr) + (size_t)e * 4;
    float s = 0.f;
#pragma unroll
    for (int i = 0; i < 4; i++) {
        float4 a = a4[i];
        s += a.x + a.y + a.z + a.w;
    }
    float ew = 1.f / (1.f + __expf(-s));

    int pos = atomicAdd(&g_cur[col], 1);
    g_se[pos] = make_int2(row, __float_as_int(ew));
}

// ---------------- fused QKV projection GEMM (bf16 MMA + ldmatrix) -----------
#define QKV_SMEM ((128 * TSTRIDE + 64 * TSTRIDE) * 4)

__global__ void __launch_bounds__(256, 3)
qkv_kernel(const float* __restrict__ x, int n)
{
    extern __shared__ unsigned smu[];
    unsigned* xs = smu;                   // [128][68] bf16x2 (64 used)
    unsigned* ws = smu + 128 * TSTRIDE;   // [64][68]  bf16x2

    const int row0 = blockIdx.x * 128;
    const int h    = blockIdx.y;
    const int tid  = threadIdx.x;
    const int warp = tid >> 5;
    const int lane = tid & 31;
    const int g    = lane >> 2;
    const int tg   = lane & 3;
    const int rb   = (warp & 3) * 32;
    const int cb   = (warp >> 2) * 32;

    const unsigned ws_base = (unsigned)__cvta_generic_to_shared(ws);
    const unsigned xs_base = (unsigned)__cvta_generic_to_shared(xs);

    const int quad = lane >> 3;
    const int r8   = lane & 7;
    unsigned aaddr[2], baddr[2];
#pragma unroll
    for (int mt = 0; mt < 2; mt++)
        aaddr[mt] = xs_base +
            ((rb + mt * 16 + (quad & 1) * 8 + r8) * TSTRIDE) * 4 +
            (quad >> 1) * 16;
#pragma unroll
    for (int p = 0; p < 2; p++)
        baddr[p] = ws_base +
            ((cb + (p * 2 + (quad >> 1)) * 8 + r8) * TSTRIDE) * 4 +
            (quad & 1) * 16;

    for (int t = tid; t < 128 * 32; t += 256) {
        int r  = t >> 5;
        int c4 = t & 31;
        float4 v = make_float4(0.f, 0.f, 0.f, 0.f);
        int gr = row0 + r;
        if (gr < n) v = reinterpret_cast<const float4*>(x)[gr * 32 + c4];
        unsigned u0 = pack_bf16x2(v.x, v.y);
        unsigned u1 = pack_bf16x2(v.z, v.w);
        unsigned long long u64v =
            (unsigned long long)u0 | ((unsigned long long)u1 << 32);
        *reinterpret_cast<unsigned long long*>(xs + r * TSTRIDE + c4 * 2) = u64v;
    }

    __nv_bfloat16* Os[3] = {g_Qh, g_Kh, g_Vh};

    for (int w = 0; w < 3; w++) {
        __syncthreads();
        const unsigned* Wsrc = g_Wb32 + (w * DMODEL + h * 64) * 64;
        for (int t = tid; t < 64 * 16; t += 256) {
            int r   = t >> 4;
            int c16 = t & 15;
            cp_async16(ws_base + (r * TSTRIDE + c16 * 4) * 4,
                       Wsrc + r * 64 + c16 * 4);
        }
        cp_async_wait_all();
        __syncthreads();

        float c[2][4][4];
#pragma unroll
        for (int mt = 0; mt < 2; mt++)
#pragma unroll
            for (int nt = 0; nt < 4; nt++)
#pragma unroll
                for (int i = 0; i < 4; i++) c[mt][nt][i] = 0.f;

#pragma unroll
        for (int kt = 0; kt < 8; kt++) {
            const unsigned off = kt * 32;
            unsigned a[2][4], b[2][4];
            ldmx4(a[0][0], a[0][1], a[0][2], a[0][3], aaddr[0] + off);
            ldmx4(a[1][0], a[1][1], a[1][2], a[1][3], aaddr[1] + off);
            ldmx4(b[0][0], b[0][1], b[0][2], b[0][3], baddr[0] + off);
            ldmx4(b[1][0], b[1][1], b[1][2], b[1][3], baddr[1] + off);
#pragma unroll
            for (int p = 0; p < 2; p++)
#pragma unroll
                for (int q = 0; q < 2; q++) {
                    const int nt = p * 2 + q;
                    mma_bf16(c[0][nt], a[0][0], a[0][1], a[0][2], a[0][3],
                             b[p][2 * q], b[p][2 * q + 1]);
                    mma_bf16(c[1][nt], a[1][0], a[1][1], a[1][2], a[1][3],
                             b[p][2 * q], b[p][2 * q + 1]);
                }
        }

        const float scale = (w == 0) ? 0.25f : 1.0f;
        __nv_bfloat162* OUT = reinterpret_cast<__nv_bfloat162*>(Os[w]);
#pragma unroll
        for (int mt = 0; mt < 2; mt++) {
#pragma unroll
            for (int nt = 0; nt < 4; nt++) {
                int cp = (h * 64 + cb + nt * 8 + 2 * tg) >> 1;
                int r1 = row0 + rb + mt * 16 + g;
                int r2 = r1 + 8;
                if (r1 < n)
                    OUT[r1 * 64 + cp] = __floats2bfloat162_rn(
                        c[mt][nt][0] * scale, c[mt][nt][1] * scale);
                if (r2 < n)
                    OUT[r2 * 64 + cp] = __floats2bfloat162_rn(
                        c[mt][nt][2] * scale, c[mt][nt][3] * scale);
            }
        }
    }
}

// ---------------- CSR edge aggregation (no atomics, bf16 output) -------------
__global__ void __launch_bounds__(256)
edge_agg_kernel(int n)
{
    const int gw = (blockIdx.x * blockDim.x + threadIdx.x) >> 5;
    if (gw >= n) return;
    const int lane = threadIdx.x & 31;
    const int hw   = lane >> 4;
    const int hl   = lane & 15;
    const unsigned hmask = 0xFFFFu << (hw * 16);

    const int start = __ldg(&g_off[gw]);
    const int end   = __ldg(&g_off[gw + 1]);

    const uint4* Q4 = reinterpret_cast<const uint4*>(g_Qh);
    const uint4* K4 = reinterpret_cast<const uint4*>(g_Kh);
    const uint4* V4 = reinterpret_cast<const uint4*>(g_Vh);

    uint4 ku = K4[gw * 16 + hl];
    float2 k0 = __bfloat1622float2(*reinterpret_cast<__nv_bfloat162*>(&ku.x));
    float2 k1 = __bfloat1622float2(*reinterpret_cast<__nv_bfloat162*>(&ku.y));
    float2 k2 = __bfloat1622float2(*reinterpret_cast<__nv_bfloat162*>(&ku.z));
    float2 k3 = __bfloat1622float2(*reinterpret_cast<__nv_bfloat162*>(&ku.w));

    float2 a0 = {0.f, 0.f}, a1 = {0.f, 0.f}, a2 = {0.f, 0.f}, a3 = {0.f, 0.f};

    for (int e = start + hw; e < end; e += 4) {
        const int has2 = (e + 2 < end);

        int2 se0 = __ldg(&g_se[e]);
        int2 se1 = has2 ? __ldg(&g_se[e + 2]) : se0;

        uint4 qu0 = Q4[se0.x * 16 + hl];
        uint4 vu0 = V4[se0.x * 16 + hl];
        uint4 qu1 = Q4[se1.x * 16 + hl];
        uint4 vu1 = V4[se1.x * 16 + hl];

        {
            float ew = __int_as_float(se0.y);
            float2 q0 = __bfloat1622float2(*reinterpret_cast<__nv_bfloat162*>(&qu0.x));
            float2 q1 = __bfloat1622float2(*reinterpret_cast<__nv_bfloat162*>(&qu0.y));
            float2 q2 = __bfloat1622float2(*reinterpret_cast<__nv_bfloat162*>(&qu0.z));
            float2 q3 = __bfloat1622float2(*reinterpret_cast<__nv_bfloat162*>(&qu0.w));
            float s = q0.x * k0.x + q0.y * k0.y + q1.x * k1.x + q1.y * k1.y +
                      q2.x * k2.x + q2.y * k2.y + q3.x * k3.x + q3.y * k3.y;
            s += __shfl_xor_sync(hmask, s, 1);
            s = (s > 0.f) ? s : ALPHA * s;
            s *= ew;
            float m = s;
            m = fmaxf(m, __shfl_xor_sync(hmask, m, 2));
            m = fmaxf(m, __shfl_xor_sync(hmask, m, 4));
            m = fmaxf(m, __shfl_xor_sync(hmask, m, 8));
            float p = __expf(s - m);
            float den = p;
            den += __shfl_xor_sync(hmask, den, 2);
            den += __shfl_xor_sync(hmask, den, 4);
            den += __shfl_xor_sync(hmask, den, 8);
            p /= den;
            float2 v0 = __bfloat1622float2(*reinterpret_cast<__nv_bfloat162*>(&vu0.x));
            float2 v1 = __bfloat1622float2(*reinterpret_cast<__nv_bfloat162*>(&vu0.y));
            float2 v2 = __bfloat1622float2(*reinterpret_cast<__nv_bfloat162*>(&vu0.z));
            float2 v3 = __bfloat1622float2(*reinterpret_cast<__nv_bfloat162*>(&vu0.w));
            a0.x += p * v0.x; a0.y += p * v0.y;
            a1.x += p * v1.x; a1.y += p * v1.y;
            a2.x += p * v2.x; a2.y += p * v2.y;
            a3.x += p * v3.x; a3.y += p * v3.y;
        }
        if (has2) {
            float ew = __int_as_float(se1.y);
            float2 q0 = __bfloat1622float2(*reinterpret_cast<__nv_bfloat162*>(&qu1.x));
            float2 q1 = __bfloat1622float2(*reinterpret_cast<__nv_bfloat162*>(&qu1.y));
            float2 q2 = __bfloat1622float2(*reinterpret_cast<__nv_bfloat162*>(&qu1.z));
            float2 q3 = __bfloat1622float2(*reinterpret_cast<__nv_bfloat162*>(&qu1.w));
            float s = q0.x * k0.x + q0.y * k0.y + q1.x * k1.x + q1.y * k1.y +
                      q2.x * k2.x + q2.y * k2.y + q3.x * k3.x + q3.y * k3.y;
            s += __shfl_xor_sync(hmask, s, 1);
            s = (s > 0.f) ? s : ALPHA * s;
            s *= ew;
            float m = s;
            m = fmaxf(m, __shfl_xor_sync(hmask, m, 2));
            m = fmaxf(m, __shfl_xor_sync(hmask, m, 4));
            m = fmaxf(m, __shfl_xor_sync(hmask, m, 8));
            float p = __expf(s - m);
            float den = p;
            den += __shfl_xor_sync(hmask, den, 2);
            den += __shfl_xor_sync(hmask, den, 4);
            den += __shfl_xor_sync(hmask, den, 8);
            p /= den;
            float2 v0 = __bfloat1622float2(*reinterpret_cast<__nv_bfloat162*>(&vu1.x));
            float2 v1 = __bfloat1622float2(*reinterpret_cast<__nv_bfloat162*>(&vu1.y));
            float2 v2 = __bfloat1622float2(*reinterpret_cast<__nv_bfloat162*>(&vu1.z));
            float2 v3 = __bfloat1622float2(*reinterpret_cast<__nv_bfloat162*>(&vu1.w));
            a0.x += p * v0.x; a0.y += p * v0.y;
            a1.x += p * v1.x; a1.y += p * v1.y;
            a2.x += p * v2.x; a2.y += p * v2.y;
            a3.x += p * v3.x; a3.y += p * v3.y;
        }
    }

    a0.x += __shfl_xor_sync(0xffffffffu, a0.x, 16);
    a0.y += __shfl_xor_sync(0xffffffffu, a0.y, 16);
    a1.x += __shfl_xor_sync(0xffffffffu, a1.x, 16);
    a1.y += __shfl_xor_sync(0xffffffffu, a1.y, 16);
    a2.x += __shfl_xor_sync(0xffffffffu, a2.x, 16);
    a2.y += __shfl_xor_sync(0xffffffffu, a2.y, 16);
    a3.x += __shfl_xor_sync(0xffffffffu, a3.x, 16);
    a3.y += __shfl_xor_sync(0xffffffffu, a3.y, 16);

    if (hw == 0) {
        uint4 u;
        u.x = pack_bf16x2(a0.x, a0.y);
        u.y = pack_bf16x2(a1.x, a1.y);
        u.z = pack_bf16x2(a2.x, a2.y);
        u.w = pack_bf16x2(a3.x, a3.y);
        reinterpret_cast<uint4*>(g_AGGh)[gw * 16 + hl] = u;
    }
}

// ---------------- output projection + residual + LayerNorm (bf16 MMA) -------
// A-tile copied directly from bf16 AGG via cp.async (no convert).
#define OUT_SMEM (128 * 132 * 4)

__global__ void __launch_bounds__(256, 2)
out_ln_kernel(const float* __restrict__ x,
              const float* __restrict__ bo,
              const float* __restrict__ gamma,
              const float* __restrict__ beta,
              float* __restrict__ out,
              int n)
{
    extern __shared__ unsigned smu[];
    unsigned* as = smu;                   // [128][68] bf16x2 AGG
    unsigned* ws = smu + 128 * TSTRIDE;   // [64][68]  bf16x2 Wo half
    float* res = reinterpret_cast<float*>(smu);  // [128][132] fp32 (aliases)

    const int row0 = blockIdx.x * 128;
    const int tid  = threadIdx.x;
    const int warp = tid >> 5;
    const int lane = tid & 31;
    const int g    = lane >> 2;
    const int tg   = lane & 3;
    const int rb   = (warp & 3) * 32;
    const int cb   = (warp >> 2) * 32;

    const unsigned ws_base = (unsigned)__cvta_generic_to_shared(ws);
    const unsigned as_base = (unsigned)__cvta_generic_to_shared(as);

    const int quad = lane >> 3;
    const int r8   = lane & 7;
    unsigned aaddr[2], baddr[2];
#pragma unroll
    for (int mt = 0; mt < 2; mt++)
        aaddr[mt] = as_base +
            ((rb + mt * 16 + (quad & 1) * 8 + r8) * TSTRIDE) * 4 +
            (quad >> 1) * 16;
#pragma unroll
    for (int p = 0; p < 2; p++)
        baddr[p] = ws_base +
            ((cb + (p * 2 + (quad >> 1)) * 8 + r8) * TSTRIDE) * 4 +
            (quad & 1) * 16;

    // A-tile: straight bf16 copy via cp.async (zero rows past n)
    {
        const unsigned* Asrc = reinterpret_cast<const unsigned*>(g_AGGh);
        int rmax = n - row0;
        if (rmax > 128) rmax = 128;
        for (int t = tid; t < 128 * 16; t += 256) {
            int r   = t >> 4;
            int c16 = t & 15;
            if (r < rmax) {
                cp_async16(as_base + (r * TSTRIDE + c16 * 4) * 4,
                           Asrc + (size_t)(row0 + r) * 64 + c16 * 4);
            } else {
                uint4 z = make_uint4(0, 0, 0, 0);
                *reinterpret_cast<uint4*>(as + r * TSTRIDE + c16 * 4) = z;
            }
        }
    }

    float c[2][2][4][4];
#pragma unroll
    for (int h = 0; h < 2; h++)
#pragma unroll
        for (int mt = 0; mt < 2; mt++)
#pragma unroll
            for (int nt = 0; nt < 4; nt++)
#pragma unroll
                for (int i = 0; i < 4; i++) c[h][mt][nt][i] = 0.f;

    for (int h = 0; h < 2; h++) {
        __syncthreads();
        const unsigned* Wsrc = g_Wob32 + (h * 64) * 64;
        for (int t = tid; t < 64 * 16; t += 256) {
            int r   = t >> 4;
            int c16 = t & 15;
            cp_async16(ws_base + (r * TSTRIDE + c16 * 4) * 4,
                       Wsrc + r * 64 + c16 * 4);
        }
        cp_async_wait_all();
        __syncthreads();

#pragma unroll
        for (int kt = 0; kt < 8; kt++) {
            const unsigned off = kt * 32;
            unsigned a[2][4], b[2][4];
            ldmx4(a[0][0], a[0][1], a[0][2], a[0][3], aaddr[0] + off);
            ldmx4(a[1][0], a[1][1], a[1][2], a[1][3], aaddr[1] + off);
            ldmx4(b[0][0], b[0][1], b[0][2], b[0][3], baddr[0] + off);
            ldmx4(b[1][0], b[1][1], b[1][2], b[1][3], baddr[1] + off);
#pragma unroll
            for (int p = 0; p < 2; p++)
#pragma unroll
                for (int q = 0; q < 2; q++) {
                    const int nt = p * 2 + q;
                    mma_bf16(c[h][0][nt], a[0][0], a[0][1], a[0][2], a[0][3],
                             b[p][2 * q], b[p][2 * q + 1]);
                    mma_bf16(c[h][1][nt], a[1][0], a[1][1], a[1][2], a[1][3],
                             b[p][2 * q], b[p][2 * q + 1]);
                }
        }
    }

    __syncthreads();
#pragma unroll
    for (int h = 0; h < 2; h++)
#pragma unroll
        for (int mt = 0; mt < 2; mt++)
#pragma unroll
            for (int nt = 0; nt < 4; nt++) {
                int r1 = rb + mt * 16 + g;
                int cc = h * 64 + cb + nt * 8 + 2 * tg;
                res[r1 * 132 + cc]           = c[h][mt][nt][0];
                res[r1 * 132 + cc + 1]       = c[h][mt][nt][1];
                res[(r1 + 8) * 132 + cc]     = c[h][mt][nt][2];
                res[(r1 + 8) * 132 + cc + 1] = c[h][mt][nt][3];
            }
    __syncthreads();

    float4 bo4 = reinterpret_cast<const float4*>(bo)[lane];
    float4 g4  = reinterpret_cast<const float4*>(gamma)[lane];
    float4 b4  = reinterpret_cast<const float4*>(beta)[lane];

    for (int r = warp; r < 128; r += 8) {
        int gr = row0 + r;
        if (gr >= n) continue;
        float4 a  = *reinterpret_cast<float4*>(res + r * 132 + lane * 4);
        float4 xv = reinterpret_cast<const float4*>(x)[gr * 32 + lane];
        float o0 = a.x + bo4.x + xv.x;
        float o1 = a.y + bo4.y + xv.y;
        float o2 = a.z + bo4.z + xv.z;
        float o3 = a.w + bo4.w + xv.w;

        float s  = o0 + o1 + o2 + o3;
        float ss = o0 * o0 + o1 * o1 + o2 * o2 + o3 * o3;
#pragma unroll
        for (int off = 16; off >= 1; off >>= 1) {
            s  += __shfl_xor_sync(0xffffffffu, s,  off);
            ss += __shfl_xor_sync(0xffffffffu, ss, off);
        }
        float mu  = s * (1.f / 128.f);
        float var = ss * (1.f / 128.f) - mu * mu;
        float inv = rsqrtf(var + LN_EPS);

        float4 o;
        o.x = (o0 - mu) * inv * g4.x + b4.x;
        o.y = (o1 - mu) * inv * g4.y + b4.y;
        o.z = (o2 - mu) * inv * g4.z + b4.z;
        o.w = (o3 - mu) * inv * g4.w + b4.w;
        reinterpret_cast<float4*>(out)[gr * 32 + lane] = o;
    }
}

// ---------------- launcher ---------------------------------------------------
extern "C" void kernel_launch(void* const* d_in, const int* in_sizes, int n_in,
                              void* d_out, int out_size)
{
    const float* x     = (const float*)d_in[0];
    const void*  ei    = d_in[1];
    const float* eattr = (const float*)d_in[2];
    const float* Wq    = (const float*)d_in[3];
    const float* Wk    = (const float*)d_in[4];
    const float* Wv    = (const float*)d_in[5];
    const float* Wo    = (const float*)d_in[6];
    const float* bo    = (const float*)d_in[7];
    const float* gamma = (const float*)d_in[8];
    const float* beta  = (const float*)d_in[9];
    float* out = (float*)d_out;

    int n = in_sizes[0] / DMODEL;
    int E = in_sizes[1] / 2;
    if (n > NMAX) n = NMAX;
    if (E > EMAX) E = EMAX;

    cudaFuncSetAttribute(qkv_kernel,
                         cudaFuncAttributeMaxDynamicSharedMemorySize, QKV_SMEM);
    cudaFuncSetAttribute(out_ln_kernel,
                         cudaFuncAttributeMaxDynamicSharedMemorySize, OUT_SMEM);

    int nsb = (n + SCAN_BLK - 1) / SCAN_BLK;

    wprep_kernel<<<32, 256>>>((const unsigned*)ei, Wq, Wk, Wv, Wo, n, E);
    hist_kernel<<<(E + 255) / 256, 256>>>(ei, E);
    scanA_kernel<<<nsb, 256>>>(n);
    scanC_kernel<<<(n + 255) / 256, 256>>>(n);
    scatter_kernel<<<(E + 255) / 256, 256>>>(ei, eattr, E);

    int nrb = (n + 127) / 128;
    qkv_kernel<<<dim3(nrb, 2), 256, QKV_SMEM>>>(x, n);

    edge_agg_kernel<<<(n + 7) / 8, 256>>>(n);

    out_ln_kernel<<<nrb, 256, OUT_SMEM>>>(x, bo, gamma, beta, out, n);
}

// round 17
// speedup vs baseline: 1.5976x; 1.1294x over previous
#include <cuda_runtime.h>
#include <cuda_bf16.h>
#include <math.h>

#define NMAX    50000
#define EMAX    800000
#define DMODEL  128
#define ALPHA   0.2f
#define LN_EPS  1e-5f

// K=128 bf16 => 64 u32 per row; stride 68 (4 pad) => ldmatrix rows CF.
#define TSTRIDE 68
#define SCAN_BLK 1024

// ---------------- scratch (device globals; no allocations allowed) ----------
__device__ __align__(16) __nv_bfloat16 g_Qh[NMAX * DMODEL];
__device__ __align__(16) __nv_bfloat16 g_Kh[NMAX * DMODEL];
__device__ __align__(16) __nv_bfloat16 g_Vh[NMAX * DMODEL];
__device__ __align__(16) __nv_bfloat16 g_AGGh[NMAX * DMODEL];   // bf16 AGG
__device__ __align__(16) unsigned g_Wb32[3 * DMODEL * 64];   // Wq,Wk,Wv bf16x2
__device__ __align__(16) unsigned g_Wob32[DMODEL * 64];      // Wo bf16x2
__device__ __align__(16) int   g_cnt[NMAX];
__device__ __align__(16) int   g_off[NMAX + 1];
__device__ __align__(16) int   g_cur[NMAX];
__device__ __align__(16) int   g_bsum[(NMAX + SCAN_BLK - 1) / SCAN_BLK + 1];
__device__ __align__(16) int2  g_se[EMAX + 64];   // {row, ew bits} per CSR slot
__device__ int g_is64;

// ---------------- bf16 mma / ldmatrix helpers --------------------------------
__device__ __forceinline__ void mma_bf16(float c[4],
                                         unsigned a0, unsigned a1,
                                         unsigned a2, unsigned a3,
                                         unsigned b0, unsigned b1)
{
    asm("mma.sync.aligned.m16n8k16.row.col.f32.bf16.bf16.f32 "
        "{%0,%1,%2,%3}, {%4,%5,%6,%7}, {%8,%9}, {%0,%1,%2,%3};"
        : "+f"(c[0]), "+f"(c[1]), "+f"(c[2]), "+f"(c[3])
        : "r"(a0), "r"(a1), "r"(a2), "r"(a3), "r"(b0), "r"(b1));
}

__device__ __forceinline__ void ldmx4(unsigned& r0, unsigned& r1,
                                      unsigned& r2, unsigned& r3,
                                      unsigned addr)
{
    asm volatile("ldmatrix.sync.aligned.m8n8.x4.shared.b16 {%0,%1,%2,%3}, [%4];"
                 : "=r"(r0), "=r"(r1), "=r"(r2), "=r"(r3) : "r"(addr));
}

__device__ __forceinline__ unsigned pack_bf16x2(float lo, float hi)
{
    __nv_bfloat162 h = __floats2bfloat162_rn(lo, hi);
    return *reinterpret_cast<unsigned*>(&h);
}

__device__ __forceinline__ void cp_async16(unsigned smem_dst, const void* gsrc)
{
    asm volatile("cp.async.cg.shared.global [%0], [%1], 16;"
                 :: "r"(smem_dst), "l"(gsrc));
}
__device__ __forceinline__ void cp_async_wait_all()
{
    asm volatile("cp.async.commit_group;");
    asm volatile("cp.async.wait_group 0;");
}

__device__ __forceinline__ int edge_col(const void* eiv, int E, int e)
{
    return g_is64 ? (int)reinterpret_cast<const long long*>(eiv)[(long long)E + e]
                  : reinterpret_cast<const int*>(eiv)[E + e];
}
__device__ __forceinline__ int edge_row(const void* eiv, int E, int e)
{
    return g_is64 ? (int)reinterpret_cast<const long long*>(eiv)[e]
                  : reinterpret_cast<const int*>(eiv)[e];
}

// ---------------- wprep: dtype detect + bf16 weights + zero histogram -------
__global__ void wprep_kernel(const unsigned* __restrict__ ei,
                             const float* __restrict__ Wq,
                             const float* __restrict__ Wk,
                             const float* __restrict__ Wv,
                             const float* __restrict__ Wo,
                             int n, int E)
{
    int i = blockIdx.x * blockDim.x + threadIdx.x;
    if (i == 0) {
        int is64 = 1;
        int m = (E >= 64) ? 64 : E;
        for (int j = 0; j < m; j++) {
            if (ei[2 * j + 1] != 0u) { is64 = 0; break; }
        }
        g_is64 = is64;
    }
    if (i < DMODEL * 64) {
        const float2* q2 = reinterpret_cast<const float2*>(Wq);
        const float2* k2 = reinterpret_cast<const float2*>(Wk);
        const float2* v2 = reinterpret_cast<const float2*>(Wv);
        const float2* o2 = reinterpret_cast<const float2*>(Wo);
        float2 a;
        a = q2[i]; g_Wb32[i]                   = pack_bf16x2(a.x, a.y);
        a = k2[i]; g_Wb32[DMODEL * 64 + i]     = pack_bf16x2(a.x, a.y);
        a = v2[i]; g_Wb32[2 * DMODEL * 64 + i] = pack_bf16x2(a.x, a.y);
        a = o2[i]; g_Wob32[i]                  = pack_bf16x2(a.x, a.y);
    }
    const int total = gridDim.x * blockDim.x;
    for (int j = i; j < n; j += total) g_cnt[j] = 0;
}

// ---------------- histogram of destination degrees ---------------------------
__global__ void hist_kernel(const void* __restrict__ eiv, int E)
{
    int e = blockIdx.x * blockDim.x + threadIdx.x;
    if (e >= E) return;
    atomicAdd(&g_cnt[edge_col(eiv, E, e)], 1);
}

// ---------------- two-level scan ---------------------------------------------
__global__ void scanA_kernel(int n)
{
    __shared__ int ts[256];
    const int t    = threadIdx.x;
    const int base = blockIdx.x * SCAN_BLK;
    const int idx  = base + t * 4;

    int c0 = 0, c1 = 0, c2 = 0, c3 = 0;
    if (idx + 3 < n) {
        int4 v = *reinterpret_cast<const int4*>(&g_cnt[idx]);
        c0 = v.x; c1 = v.y; c2 = v.z; c3 = v.w;
    } else {
        if (idx + 0 < n) c0 = g_cnt[idx + 0];
        if (idx + 1 < n) c1 = g_cnt[idx + 1];
        if (idx + 2 < n) c2 = g_cnt[idx + 2];
        if (idx + 3 < n) c3 = g_cnt[idx + 3];
    }
    int s = c0 + c1 + c2 + c3;
    ts[t] = s;
    __syncthreads();
#pragma unroll
    for (int off = 1; off < 256; off <<= 1) {
        int v = (t >= off) ? ts[t - off] : 0;
        __syncthreads();
        ts[t] += v;
        __syncthreads();
    }
    int run = (t == 0) ? 0 : ts[t - 1];
    if (idx + 0 < n) { g_off[idx + 0] = run; run += c0; }
    if (idx + 1 < n) { g_off[idx + 1] = run; run += c1; }
    if (idx + 2 < n) { g_off[idx + 2] = run; run += c2; }
    if (idx + 3 < n) { g_off[idx + 3] = run; run += c3; }
    if (t == 255) g_bsum[blockIdx.x] = ts[255];
}

__global__ void scanC_kernel(int n)
{
    __shared__ int boff_s;
    const int chunk = blockIdx.x >> 2;
    if (threadIdx.x < 32) {
        int v = 0;
        for (int j = threadIdx.x; j < chunk; j += 32) v += g_bsum[j];
#pragma unroll
        for (int off = 16; off >= 1; off >>= 1)
            v += __shfl_xor_sync(0xffffffffu, v, off);
        if (threadIdx.x == 0) boff_s = v;
    }
    __syncthreads();
    int i = blockIdx.x * 256 + threadIdx.x;
    if (i >= n) return;
    int o = g_off[i] + boff_s;
    g_off[i] = o;
    g_cur[i] = o;
    if (i == n - 1) g_off[n] = o + g_cnt[i];
}

// ---------------- scatter: permute (row, gate) into CSR order ----------------
__global__ void scatter_kernel(const void* __restrict__ eiv,
                               const float* __restrict__ eattr,
                               int E)
{
    int e = blockIdx.x * blockDim.x + threadIdx.x;
    if (e >= E) return;
    int row = edge_row(eiv, E, e);
    int col = edge_col(eiv, E, e);

    const float4* a4 = reinterpret_cast<const float4*>(eattr) + (size_t)e * 4;
    float s = 0.f;
#pragma unroll
    for (int i = 0; i < 4; i++) {
        float4 a = a4[i];
        s += a.x + a.y + a.z + a.w;
    }
    float ew = 1.f / (1.f + __expf(-s));

    int pos = atomicAdd(&g_cur[col], 1);
    g_se[pos] = make_int2(row, __float_as_int(ew));
}

// ---------------- fused QKV projection GEMM (bf16 MMA + ldmatrix) -----------
#define QKV_SMEM ((128 * TSTRIDE + 64 * TSTRIDE) * 4)

__global__ void __launch_bounds__(256, 3)
qkv_kernel(const float* __restrict__ x, int n)
{
    extern __shared__ unsigned smu[];
    unsigned* xs = smu;                   // [128][68] bf16x2 (64 used)
    unsigned* ws = smu + 128 * TSTRIDE;   // [64][68]  bf16x2

    const int row0 = blockIdx.x * 128;
    const int h    = blockIdx.y;
    const int tid  = threadIdx.x;
    const int warp = tid >> 5;
    const int lane = tid & 31;
    const int g    = lane >> 2;
    const int tg   = lane & 3;
    const int rb   = (warp & 3) * 32;
    const int cb   = (warp >> 2) * 32;

    const unsigned ws_base = (unsigned)__cvta_generic_to_shared(ws);
    const unsigned xs_base = (unsigned)__cvta_generic_to_shared(xs);

    const int quad = lane >> 3;
    const int r8   = lane & 7;
    unsigned aaddr[2], baddr[2];
#pragma unroll
    for (int mt = 0; mt < 2; mt++)
        aaddr[mt] = xs_base +
            ((rb + mt * 16 + (quad & 1) * 8 + r8) * TSTRIDE) * 4 +
            (quad >> 1) * 16;
#pragma unroll
    for (int p = 0; p < 2; p++)
        baddr[p] = ws_base +
            ((cb + (p * 2 + (quad >> 1)) * 8 + r8) * TSTRIDE) * 4 +
            (quad & 1) * 16;

    for (int t = tid; t < 128 * 32; t += 256) {
        int r  = t >> 5;
        int c4 = t & 31;
        float4 v = make_float4(0.f, 0.f, 0.f, 0.f);
        int gr = row0 + r;
        if (gr < n) v = reinterpret_cast<const float4*>(x)[gr * 32 + c4];
        unsigned u0 = pack_bf16x2(v.x, v.y);
        unsigned u1 = pack_bf16x2(v.z, v.w);
        unsigned long long u64v =
            (unsigned long long)u0 | ((unsigned long long)u1 << 32);
        *reinterpret_cast<unsigned long long*>(xs + r * TSTRIDE + c4 * 2) = u64v;
    }

    __nv_bfloat16* Os[3] = {g_Qh, g_Kh, g_Vh};

    for (int w = 0; w < 3; w++) {
        __syncthreads();
        const unsigned* Wsrc = g_Wb32 + (w * DMODEL + h * 64) * 64;
        for (int t = tid; t < 64 * 16; t += 256) {
            int r   = t >> 4;
            int c16 = t & 15;
            cp_async16(ws_base + (r * TSTRIDE + c16 * 4) * 4,
                       Wsrc + r * 64 + c16 * 4);
        }
        cp_async_wait_all();
        __syncthreads();

        float c[2][4][4];
#pragma unroll
        for (int mt = 0; mt < 2; mt++)
#pragma unroll
            for (int nt = 0; nt < 4; nt++)
#pragma unroll
                for (int i = 0; i < 4; i++) c[mt][nt][i] = 0.f;

#pragma unroll
        for (int kt = 0; kt < 8; kt++) {
            const unsigned off = kt * 32;
            unsigned a[2][4], b[2][4];
            ldmx4(a[0][0], a[0][1], a[0][2], a[0][3], aaddr[0] + off);
            ldmx4(a[1][0], a[1][1], a[1][2], a[1][3], aaddr[1] + off);
            ldmx4(b[0][0], b[0][1], b[0][2], b[0][3], baddr[0] + off);
            ldmx4(b[1][0], b[1][1], b[1][2], b[1][3], baddr[1] + off);
#pragma unroll
            for (int p = 0; p < 2; p++)
#pragma unroll
                for (int q = 0; q < 2; q++) {
                    const int nt = p * 2 + q;
                    mma_bf16(c[0][nt], a[0][0], a[0][1], a[0][2], a[0][3],
                             b[p][2 * q], b[p][2 * q + 1]);
                    mma_bf16(c[1][nt], a[1][0], a[1][1], a[1][2], a[1][3],
                             b[p][2 * q], b[p][2 * q + 1]);
                }
        }

        const float scale = (w == 0) ? 0.25f : 1.0f;
        __nv_bfloat162* OUT = reinterpret_cast<__nv_bfloat162*>(Os[w]);
#pragma unroll
        for (int mt = 0; mt < 2; mt++) {
#pragma unroll
            for (int nt = 0; nt < 4; nt++) {
                int cp = (h * 64 + cb + nt * 8 + 2 * tg) >> 1;
                int r1 = row0 + rb + mt * 16 + g;
                int r2 = r1 + 8;
                if (r1 < n)
                    OUT[r1 * 64 + cp] = __floats2bfloat162_rn(
                        c[mt][nt][0] * scale, c[mt][nt][1] * scale);
                if (r2 < n)
                    OUT[r2 * 64 + cp] = __floats2bfloat162_rn(
                        c[mt][nt][2] * scale, c[mt][nt][3] * scale);
            }
        }
    }
}

// ---------------- CSR edge aggregation (no atomics, bf16 output) -------------
__global__ void __launch_bounds__(256)
edge_agg_kernel(int n)
{
    const int gw = (blockIdx.x * blockDim.x + threadIdx.x) >> 5;
    if (gw >= n) return;
    const int lane = threadIdx.x & 31;
    const int hw   = lane >> 4;
    const int hl   = lane & 15;
    const unsigned hmask = 0xFFFFu << (hw * 16);

    const int start = __ldg(&g_off[gw]);
    const int end   = __ldg(&g_off[gw + 1]);

    const uint4* Q4 = reinterpret_cast<const uint4*>(g_Qh);
    const uint4* K4 = reinterpret_cast<const uint4*>(g_Kh);
    const uint4* V4 = reinterpret_cast<const uint4*>(g_Vh);

    uint4 ku = K4[gw * 16 + hl];
    float2 k0 = __bfloat1622float2(*reinterpret_cast<__nv_bfloat162*>(&ku.x));
    float2 k1 = __bfloat1622float2(*reinterpret_cast<__nv_bfloat162*>(&ku.y));
    float2 k2 = __bfloat1622float2(*reinterpret_cast<__nv_bfloat162*>(&ku.z));
    float2 k3 = __bfloat1622float2(*reinterpret_cast<__nv_bfloat162*>(&ku.w));

    float2 a0 = {0.f, 0.f}, a1 = {0.f, 0.f}, a2 = {0.f, 0.f}, a3 = {0.f, 0.f};

    for (int e = start + hw; e < end; e += 4) {
        const int has2 = (e + 2 < end);

        int2 se0 = __ldg(&g_se[e]);
        int2 se1 = has2 ? __ldg(&g_se[e + 2]) : se0;

        uint4 qu0 = Q4[se0.x * 16 + hl];
        uint4 vu0 = V4[se0.x * 16 + hl];
        uint4 qu1 = Q4[se1.x * 16 + hl];
        uint4 vu1 = V4[se1.x * 16 + hl];

        {
            float ew = __int_as_float(se0.y);
            float2 q0 = __bfloat1622float2(*reinterpret_cast<__nv_bfloat162*>(&qu0.x));
            float2 q1 = __bfloat1622float2(*reinterpret_cast<__nv_bfloat162*>(&qu0.y));
            float2 q2 = __bfloat1622float2(*reinterpret_cast<__nv_bfloat162*>(&qu0.z));
            float2 q3 = __bfloat1622float2(*reinterpret_cast<__nv_bfloat162*>(&qu0.w));
            float s = q0.x * k0.x + q0.y * k0.y + q1.x * k1.x + q1.y * k1.y +
                      q2.x * k2.x + q2.y * k2.y + q3.x * k3.x + q3.y * k3.y;
            s += __shfl_xor_sync(hmask, s, 1);
            s = (s > 0.f) ? s : ALPHA * s;
            s *= ew;
            float m = s;
            m = fmaxf(m, __shfl_xor_sync(hmask, m, 2));
            m = fmaxf(m, __shfl_xor_sync(hmask, m, 4));
            m = fmaxf(m, __shfl_xor_sync(hmask, m, 8));
            float p = __expf(s - m);
            float den = p;
            den += __shfl_xor_sync(hmask, den, 2);
            den += __shfl_xor_sync(hmask, den, 4);
            den += __shfl_xor_sync(hmask, den, 8);
            p /= den;
            float2 v0 = __bfloat1622float2(*reinterpret_cast<__nv_bfloat162*>(&vu0.x));
            float2 v1 = __bfloat1622float2(*reinterpret_cast<__nv_bfloat162*>(&vu0.y));
            float2 v2 = __bfloat1622float2(*reinterpret_cast<__nv_bfloat162*>(&vu0.z));
            float2 v3 = __bfloat1622float2(*reinterpret_cast<__nv_bfloat162*>(&vu0.w));
            a0.x += p * v0.x; a0.y += p * v0.y;
            a1.x += p * v1.x; a1.y += p * v1.y;
            a2.x += p * v2.x; a2.y += p * v2.y;
            a3.x += p * v3.x; a3.y += p * v3.y;
        }
        if (has2) {
            float ew = __int_as_float(se1.y);
            float2 q0 = __bfloat1622float2(*reinterpret_cast<__nv_bfloat162*>(&qu1.x));
            float2 q1 = __bfloat1622float2(*reinterpret_cast<__nv_bfloat162*>(&qu1.y));
            float2 q2 = __bfloat1622float2(*reinterpret_cast<__nv_bfloat162*>(&qu1.z));
            float2 q3 = __bfloat1622float2(*reinterpret_cast<__nv_bfloat162*>(&qu1.w));
            float s = q0.x * k0.x + q0.y * k0.y + q1.x * k1.x + q1.y * k1.y +
                      q2.x * k2.x + q2.y * k2.y + q3.x * k3.x + q3.y * k3.y;
            s += __shfl_xor_sync(hmask, s, 1);
            s = (s > 0.f) ? s : ALPHA * s;
            s *= ew;
            float m = s;
            m = fmaxf(m, __shfl_xor_sync(hmask, m, 2));
            m = fmaxf(m, __shfl_xor_sync(hmask, m, 4));
            m = fmaxf(m, __shfl_xor_sync(hmask, m, 8));
            float p = __expf(s - m);
            float den = p;
            den += __shfl_xor_sync(hmask, den, 2);
            den += __shfl_xor_sync(hmask, den, 4);
            den += __shfl_xor_sync(hmask, den, 8);
            p /= den;
            float2 v0 = __bfloat1622float2(*reinterpret_cast<__nv_bfloat162*>(&vu1.x));
            float2 v1 = __bfloat1622float2(*reinterpret_cast<__nv_bfloat162*>(&vu1.y));
            float2 v2 = __bfloat1622float2(*reinterpret_cast<__nv_bfloat162*>(&vu1.z));
            float2 v3 = __bfloat1622float2(*reinterpret_cast<__nv_bfloat162*>(&vu1.w));
            a0.x += p * v0.x; a0.y += p * v0.y;
            a1.x += p * v1.x; a1.y += p * v1.y;
            a2.x += p * v2.x; a2.y += p * v2.y;
            a3.x += p * v3.x; a3.y += p * v3.y;
        }
    }

    a0.x += __shfl_xor_sync(0xffffffffu, a0.x, 16);
    a0.y += __shfl_xor_sync(0xffffffffu, a0.y, 16);
    a1.x += __shfl_xor_sync(0xffffffffu, a1.x, 16);
    a1.y += __shfl_xor_sync(0xffffffffu, a1.y, 16);
    a2.x += __shfl_xor_sync(0xffffffffu, a2.x, 16);
    a2.y += __shfl_xor_sync(0xffffffffu, a2.y, 16);
    a3.x += __shfl_xor_sync(0xffffffffu, a3.x, 16);
    a3.y += __shfl_xor_sync(0xffffffffu, a3.y, 16);

    if (hw == 0) {
        uint4 u;
        u.x = pack_bf16x2(a0.x, a0.y);
        u.y = pack_bf16x2(a1.x, a1.y);
        u.z = pack_bf16x2(a2.x, a2.y);
        u.w = pack_bf16x2(a3.x, a3.y);
        reinterpret_cast<uint4*>(g_AGGh)[gw * 16 + hl] = u;
    }
}

// ---------------- output projection + residual + LayerNorm (bf16 MMA) -------
#define OUT_SMEM (128 * 132 * 4)

__global__ void __launch_bounds__(256, 2)
out_ln_kernel(const float* __restrict__ x,
              const float* __restrict__ bo,
              const float* __restrict__ gamma,
              const float* __restrict__ beta,
              float* __restrict__ out,
              int n)
{
    extern __shared__ unsigned smu[];
    unsigned* as = smu;                   // [128][68] bf16x2 AGG
    unsigned* ws = smu + 128 * TSTRIDE;   // [64][68]  bf16x2 Wo half
    float* res = reinterpret_cast<float*>(smu);  // [128][132] fp32 (aliases)

    const int row0 = blockIdx.x * 128;
    const int tid  = threadIdx.x;
    const int warp = tid >> 5;
    const int lane = tid & 31;
    const int g    = lane >> 2;
    const int tg   = lane & 3;
    const int rb   = (warp & 3) * 32;
    const int cb   = (warp >> 2) * 32;

    const unsigned ws_base = (unsigned)__cvta_generic_to_shared(ws);
    const unsigned as_base = (unsigned)__cvta_generic_to_shared(as);

    const int quad = lane >> 3;
    const int r8   = lane & 7;
    unsigned aaddr[2], baddr[2];
#pragma unroll
    for (int mt = 0; mt < 2; mt++)
        aaddr[mt] = as_base +
            ((rb + mt * 16 + (quad & 1) * 8 + r8) * TSTRIDE) * 4 +
            (quad >> 1) * 16;
#pragma unroll
    for (int p = 0; p < 2; p++)
        baddr[p] = ws_base +
            ((cb + (p * 2 + (quad >> 1)) * 8 + r8) * TSTRIDE) * 4 +
            (quad & 1) * 16;

    // A-tile: straight bf16 copy via cp.async (zero rows past n)
    {
        const unsigned* Asrc = reinterpret_cast<const unsigned*>(g_AGGh);
        int rmax = n - row0;
        if (rmax > 128) rmax = 128;
        for (int t = tid; t < 128 * 16; t += 256) {
            int r   = t >> 4;
            int c16 = t & 15;
            if (r < rmax) {
                cp_async16(as_base + (r * TSTRIDE + c16 * 4) * 4,
                           Asrc + (size_t)(row0 + r) * 64 + c16 * 4);
            } else {
                uint4 z = make_uint4(0, 0, 0, 0);
                *reinterpret_cast<uint4*>(as + r * TSTRIDE + c16 * 4) = z;
            }
        }
    }

    float c[2][2][4][4];
#pragma unroll
    for (int h = 0; h < 2; h++)
#pragma unroll
        for (int mt = 0; mt < 2; mt++)
#pragma unroll
            for (int nt = 0; nt < 4; nt++)
#pragma unroll
                for (int i = 0; i < 4; i++) c[h][mt][nt][i] = 0.f;

    for (int h = 0; h < 2; h++) {
        __syncthreads();
        const unsigned* Wsrc = g_Wob32 + (h * 64) * 64;
        for (int t = tid; t < 64 * 16; t += 256) {
            int r   = t >> 4;
            int c16 = t & 15;
            cp_async16(ws_base + (r * TSTRIDE + c16 * 4) * 4,
                       Wsrc + r * 64 + c16 * 4);
        }
        cp_async_wait_all();
        __syncthreads();

#pragma unroll
        for (int kt = 0; kt < 8; kt++) {
            const unsigned off = kt * 32;
            unsigned a[2][4], b[2][4];
            ldmx4(a[0][0], a[0][1], a[0][2], a[0][3], aaddr[0] + off);
            ldmx4(a[1][0], a[1][1], a[1][2], a[1][3], aaddr[1] + off);
            ldmx4(b[0][0], b[0][1], b[0][2], b[0][3], baddr[0] + off);
            ldmx4(b[1][0], b[1][1], b[1][2], b[1][3], baddr[1] + off);
#pragma unroll
            for (int p = 0; p < 2; p++)
#pragma unroll
                for (int q = 0; q < 2; q++) {
                    const int nt = p * 2 + q;
                    mma_bf16(c[h][0][nt], a[0][0], a[0][1], a[0][2], a[0][3],
                             b[p][2 * q], b[p][2 * q + 1]);
                    mma_bf16(c[h][1][nt], a[1][0], a[1][1], a[1][2], a[1][3],
                             b[p][2 * q], b[p][2 * q + 1]);
                }
        }
    }

    __syncthreads();
#pragma unroll
    for (int h = 0; h < 2; h++)
#pragma unroll
        for (int mt = 0; mt < 2; mt++)
#pragma unroll
            for (int nt = 0; nt < 4; nt++) {
                int r1 = rb + mt * 16 + g;
                int cc = h * 64 + cb + nt * 8 + 2 * tg;
                res[r1 * 132 + cc]           = c[h][mt][nt][0];
                res[r1 * 132 + cc + 1]       = c[h][mt][nt][1];
                res[(r1 + 8) * 132 + cc]     = c[h][mt][nt][2];
                res[(r1 + 8) * 132 + cc + 1] = c[h][mt][nt][3];
            }
    __syncthreads();

    float4 bo4 = reinterpret_cast<const float4*>(bo)[lane];
    float4 g4  = reinterpret_cast<const float4*>(gamma)[lane];
    float4 b4  = reinterpret_cast<const float4*>(beta)[lane];

    for (int r = warp; r < 128; r += 8) {
        int gr = row0 + r;
        if (gr >= n) continue;
        float4 a  = *reinterpret_cast<float4*>(res + r * 132 + lane * 4);
        float4 xv = reinterpret_cast<const float4*>(x)[gr * 32 + lane];
        float o0 = a.x + bo4.x + xv.x;
        float o1 = a.y + bo4.y + xv.y;
        float o2 = a.z + bo4.z + xv.z;
        float o3 = a.w + bo4.w + xv.w;

        float s  = o0 + o1 + o2 + o3;
        float ss = o0 * o0 + o1 * o1 + o2 * o2 + o3 * o3;
#pragma unroll
        for (int off = 16; off >= 1; off >>= 1) {
            s  += __shfl_xor_sync(0xffffffffu, s,  off);
            ss += __shfl_xor_sync(0xffffffffu, ss, off);
        }
        float mu  = s * (1.f / 128.f);
        float var = ss * (1.f / 128.f) - mu * mu;
        float inv = rsqrtf(var + LN_EPS);

        float4 o;
        o.x = (o0 - mu) * inv * g4.x + b4.x;
        o.y = (o1 - mu) * inv * g4.y + b4.y;
        o.z = (o2 - mu) * inv * g4.z + b4.z;
        o.w = (o3 - mu) * inv * g4.w + b4.w;
        reinterpret_cast<float4*>(out)[gr * 32 + lane] = o;
    }
}

// ---------------- launcher ---------------------------------------------------
extern "C" void kernel_launch(void* const* d_in, const int* in_sizes, int n_in,
                              void* d_out, int out_size)
{
    const float* x     = (const float*)d_in[0];
    const void*  ei    = d_in[1];
    const float* eattr = (const float*)d_in[2];
    const float* Wq    = (const float*)d_in[3];
    const float* Wk    = (const float*)d_in[4];
    const float* Wv    = (const float*)d_in[5];
    const float* Wo    = (const float*)d_in[6];
    const float* bo    = (const float*)d_in[7];
    const float* gamma = (const float*)d_in[8];
    const float* beta  = (const float*)d_in[9];
    float* out = (float*)d_out;

    int n = in_sizes[0] / DMODEL;
    int E = in_sizes[1] / 2;
    if (n > NMAX) n = NMAX;
    if (E > EMAX) E = EMAX;

    cudaFuncSetAttribute(qkv_kernel,
                         cudaFuncAttributeMaxDynamicSharedMemorySize, QKV_SMEM);
    cudaFuncSetAttribute(out_ln_kernel,
                         cudaFuncAttributeMaxDynamicSharedMemorySize, OUT_SMEM);

    // One-time stream/event creation (first call is the pre-capture
    // correctness run; resources are reused identically on every call,
    // so captured graphs are deterministic).
    static cudaStream_t s2 = nullptr;
    static cudaEvent_t ev0 = nullptr, ev1 = nullptr;
    if (s2 == nullptr) {
        cudaStreamCreateWithFlags(&s2, cudaStreamNonBlocking);
        cudaEventCreateWithFlags(&ev0, cudaEventDisableTiming);
        cudaEventCreateWithFlags(&ev1, cudaEventDisableTiming);
    }

    int nsb = (n + SCAN_BLK - 1) / SCAN_BLK;
    int nrb = (n + 127) / 128;

    // main stream: weight prep (also zeroes histogram, detects dtype)
    wprep_kernel<<<32, 256>>>((const unsigned*)ei, Wq, Wk, Wv, Wo, n, E);

    // fork: CSR prep chain on s2, QKV GEMM on main (independent)
    cudaEventRecord(ev0, 0);
    cudaStreamWaitEvent(s2, ev0, 0);

    hist_kernel<<<(E + 255) / 256, 256, 0, s2>>>(ei, E);
    scanA_kernel<<<nsb, 256, 0, s2>>>(n);
    scanC_kernel<<<(n + 255) / 256, 256, 0, s2>>>(n);
    scatter_kernel<<<(E + 255) / 256, 256, 0, s2>>>(ei, eattr, E);
    cudaEventRecord(ev1, s2);

    qkv_kernel<<<dim3(nrb, 2), 256, QKV_SMEM>>>(x, n);

    // join: edge aggregation needs both QKV and the CSR
    cudaStreamWaitEvent(0, ev1, 0);
    edge_agg_kernel<<<(n + 7) / 8, 256>>>(n);

    out_ln_kernel<<<nrb, 256, OUT_SMEM>>>(x, bo, gamma, beta, out, n);
}